// round 4
// baseline (speedup 1.0000x reference)
#include <cuda_runtime.h>
#include <cstdint>

#define NB 64
#define NT 8
#define ND 512
#define NS 512
#define NKV 4
#define NG 2
#define EPSV 1e-6f
#define SCALEV 0.04419417382415922f  /* 512^-0.5 */

// ---------------- scratch (device globals; no allocations) ----------------
__device__ float g_qprime[NB * NT * ND];            // q rms-normed * (1+qw)*(1+kw)
__device__ float g_qW[NB * NKV * NG * ND];          // q' @ Wk_n
__device__ float g_part[NB * NS * NKV * 4];         // partial sumsq per (row, kv-head, col-subtile)
__device__ float g_rnorm[NB * NS * NKV];            // rsqrt(mean k^2 + eps)

// ---------------- helpers ----------------
__device__ __forceinline__ float warp_sum(float v) {
#pragma unroll
    for (int o = 16; o; o >>= 1) v += __shfl_xor_sync(0xffffffffu, v, o);
    return v;
}
__device__ __forceinline__ float warp_max(float v) {
#pragma unroll
    for (int o = 16; o; o >>= 1) v = fmaxf(v, __shfl_xor_sync(0xffffffffu, v, o));
    return v;
}

// =====================================================================
// Kernel 1: q = rmsnorm(target @ Wq^T, qw) * (1+kw)   (folded)
// grid = 512 (one block per (b,t) row), 256 threads
// =====================================================================
__global__ __launch_bounds__(256) void q_kernel(
    const float* __restrict__ tgt, const float* __restrict__ Wq,
    const float* __restrict__ qnw, const float* __restrict__ knw) {
    __shared__ float sx[ND];
    __shared__ float srow[ND];
    __shared__ float sred[8];
    int r = blockIdx.x;
    int tid = threadIdx.x, warp = tid >> 5, lane = tid & 31;

    for (int d = tid; d < ND; d += 256) sx[d] = tgt[r * ND + d];
    __syncthreads();

    for (int e = warp; e < ND; e += 8) {
        const float* wr = Wq + e * ND;
        float c = 0.f;
#pragma unroll
        for (int j = 0; j < 16; j++) {
            int d = lane + 32 * j;
            c += sx[d] * wr[d];
        }
        c = warp_sum(c);
        if (lane == 0) srow[e] = c;
    }
    __syncthreads();

    float ss = 0.f;
    for (int d = tid; d < ND; d += 256) { float v = srow[d]; ss += v * v; }
    ss = warp_sum(ss);
    if (lane == 0) sred[warp] = ss;
    __syncthreads();
    if (tid == 0) {
        float t = 0.f;
#pragma unroll
        for (int i = 0; i < 8; i++) t += sred[i];
        sred[0] = rsqrtf(t * (1.0f / ND) + EPSV);
    }
    __syncthreads();
    float rn = sred[0];
    for (int d = tid; d < ND; d += 256)
        g_qprime[r * ND + d] = srow[d] * rn * (1.f + qnw[d]) * (1.f + knw[d]);
}

// =====================================================================
// Kernel 2: qW[b,n,g,:] = q'[b, n*G+g, :] @ Wk_n   (contract over d)
// grid = 256 (b,n), 256 threads; each thread owns cols e=tid and e=tid+256
// =====================================================================
__global__ __launch_bounds__(256) void qw_kernel(const float* __restrict__ Wk) {
    __shared__ float sq[2][ND];
    int b = blockIdx.x >> 2, n = blockIdx.x & 3;
    int tid = threadIdx.x;
    for (int g = 0; g < 2; g++)
        for (int d = tid; d < ND; d += 256)
            sq[g][d] = g_qprime[((b * NT) + n * NG + g) * ND + d];
    __syncthreads();

    float c00 = 0.f, c01 = 0.f, c10 = 0.f, c11 = 0.f;
    const float* wb = Wk + (size_t)(n * ND) * ND;
#pragma unroll 4
    for (int d = 0; d < ND; d++) {
        float w0 = wb[(size_t)d * ND + tid];
        float w1 = wb[(size_t)d * ND + tid + 256];
        float s0 = sq[0][d], s1 = sq[1][d];
        c00 += s0 * w0; c01 += s0 * w1;
        c10 += s1 * w0; c11 += s1 * w1;
    }
    size_t base = ((size_t)(b * NKV + n) * NG) * ND;
    g_qW[base + tid] = c00; g_qW[base + tid + 256] = c01;
    g_qW[base + ND + tid] = c10; g_qW[base + ND + tid + 256] = c11;
}

// =====================================================================
// Kernel 3: K-norm GEMM — sumsq of rows of (hist @ Wk^T), tiled 128x128x8,
// fp32 via packed fma.rn.f32x2 (Blackwell 2x fp32). Writes partials only.
// grid = (16, 256), 256 threads
// =====================================================================
#define BM 128
#define BN 128
#define BK 8

__global__ __launch_bounds__(256, 2) void knorm_gemm(
    const float* __restrict__ A, const float* __restrict__ W) {
    __shared__ __align__(16) float As[BK][BM];
    __shared__ __align__(16) float Bs[BK][BN];

    int tid = threadIdx.x;
    int bm = blockIdx.y * BM;
    int bn = blockIdx.x * BN;
    int tx = tid & 15, ty = tid >> 4;

    int lrow = tid >> 1;
    int lcol = (tid & 1) * 4;
    const float* Aptr = A + (size_t)(bm + lrow) * 512 + lcol;
    const float* Wptr = W + (size_t)(bn + lrow) * 512 + lcol;

    unsigned long long acc[4][8];
#pragma unroll
    for (int i = 0; i < 4; i++)
#pragma unroll
        for (int j = 0; j < 8; j++) acc[i][j] = 0ULL;

    float4 pa = *(const float4*)(Aptr);
    float4 pw = *(const float4*)(Wptr);

#pragma unroll 1
    for (int kt = 0; kt < 512 / BK; kt++) {
        As[lcol + 0][lrow] = pa.x; As[lcol + 1][lrow] = pa.y;
        As[lcol + 2][lrow] = pa.z; As[lcol + 3][lrow] = pa.w;
        Bs[lcol + 0][lrow] = pw.x; Bs[lcol + 1][lrow] = pw.y;
        Bs[lcol + 2][lrow] = pw.z; Bs[lcol + 3][lrow] = pw.w;
        __syncthreads();
        if (kt < 512 / BK - 1) {
            pa = *(const float4*)(Aptr + (kt + 1) * BK);
            pw = *(const float4*)(Wptr + (kt + 1) * BK);
        }
#pragma unroll
        for (int k = 0; k < BK; k++) {
            ulonglong2 aa01 = *(const ulonglong2*)&As[k][ty * 8];
            ulonglong2 aa23 = *(const ulonglong2*)&As[k][ty * 8 + 4];
            float4 b0 = *(const float4*)&Bs[k][tx * 8];
            float4 b1 = *(const float4*)&Bs[k][tx * 8 + 4];
            unsigned long long aa[4] = {aa01.x, aa01.y, aa23.x, aa23.y};
            float bv[8] = {b0.x, b0.y, b0.z, b0.w, b1.x, b1.y, b1.z, b1.w};
#pragma unroll
            for (int j = 0; j < 8; j++) {
                unsigned long long bb;
                unsigned br = __float_as_uint(bv[j]);
                asm("mov.b64 %0, {%1,%2};" : "=l"(bb) : "r"(br), "r"(br));
#pragma unroll
                for (int i2 = 0; i2 < 4; i2++)
                    asm("fma.rn.f32x2 %0, %1, %2, %3;"
                        : "=l"(acc[i2][j])
                        : "l"(aa[i2]), "l"(bb), "l"(acc[i2][j]));
            }
        }
        __syncthreads();
    }

    // epilogue: per-row sum of squares across this 128-col tile
    float rs[8];
#pragma unroll
    for (int i = 0; i < 8; i++) rs[i] = 0.f;
#pragma unroll
    for (int i2 = 0; i2 < 4; i2++)
#pragma unroll
        for (int j = 0; j < 8; j++) {
            unsigned lo, hi;
            asm("mov.b64 {%0,%1}, %2;" : "=r"(lo), "=r"(hi) : "l"(acc[i2][j]));
            float flo = __uint_as_float(lo), fhi = __uint_as_float(hi);
            rs[2 * i2] += flo * flo;
            rs[2 * i2 + 1] += fhi * fhi;
        }
#pragma unroll
    for (int i = 0; i < 8; i++) {
#pragma unroll
        for (int o = 1; o < 16; o <<= 1)
            rs[i] += __shfl_xor_sync(0xffffffffu, rs[i], o);
    }
    if (tx == 0) {
        int chunk = bn >> 9;          // which kv head (512-col group)
        int sub = (bn >> 7) & 3;      // which 128-col subtile within group
#pragma unroll
        for (int i = 0; i < 8; i++) {
            int row = bm + ty * 8 + i;
            g_part[((size_t)row * NKV + chunk) * 4 + sub] = rs[i];
        }
    }
}

// =====================================================================
// Kernel 4: finalize rnorm = rsqrt(mean + eps)
// =====================================================================
__global__ void rnorm_fin() {
    int i = blockIdx.x * 256 + threadIdx.x;  // 0..131071
    float s = g_part[i * 4 + 0] + g_part[i * 4 + 1] +
              g_part[i * 4 + 2] + g_part[i * 4 + 3];
    g_rnorm[i] = rsqrtf(s * (1.0f / ND) + EPSV);
}

// =====================================================================
// Kernel 5: attention per (b,n): scores via qW·hist, softmax,
// out = (attn @ hist) @ Wv_n^T. Writes tokens + attn weights.
// grid = 256 (b,n), 256 threads
// NOTE: mask is read as 4-byte words (uint) — harness serializes bool as
// int32 or float32; "word != 0" is correct for both (0 / 1 / 1.0f).
// =====================================================================
__global__ __launch_bounds__(256) void attn_kernel(
    const float* __restrict__ hist, const unsigned int* __restrict__ mask,
    const float* __restrict__ Wv, float* __restrict__ out) {
    __shared__ float sqW[2][ND];
    __shared__ float sattn[2][NS];
    __shared__ float sah[2][ND];
    __shared__ float sred[8];

    int b = blockIdx.x >> 2, n = blockIdx.x & 3;
    int tid = threadIdx.x, warp = tid >> 5, lane = tid & 31;
    const float NEGINF = __int_as_float(0xff800000);

    size_t qbase = ((size_t)(b * NKV + n) * NG) * ND;
    for (int g = 0; g < 2; g++)
        for (int e = tid; e < ND; e += 256) sqW[g][e] = g_qW[qbase + g * ND + e];
    __syncthreads();

    // ---- Phase A: scores[g][s] = rnorm_s * SCALE * dot(qW[g], hist[b,s,:]) + bias
    const float* hb = hist + (size_t)b * NS * ND;
    for (int s = warp; s < NS; s += 8) {
        const float* hrow = hb + (size_t)s * ND;
        float a0 = 0.f, a1 = 0.f;
#pragma unroll
        for (int j = 0; j < 16; j++) {
            int d = lane + 32 * j;
            float h = hrow[d];
            a0 += h * sqW[0][d];
            a1 += h * sqW[1][d];
        }
        a0 = warp_sum(a0);
        a1 = warp_sum(a1);
        if (lane == 0) {
            float rn = g_rnorm[((size_t)b * NS + s) * NKV + n];
            float bias = (mask[b * NS + s] != 0u) ? NEGINF : 0.f;
            sattn[0][s] = a0 * rn * SCALEV + bias;
            sattn[1][s] = a1 * rn * SCALEV + bias;
        }
    }
    __syncthreads();

    // ---- Phase B: softmax per g, write attn weights
    float* wout = out + (size_t)NB * NT * ND;
    for (int g = 0; g < 2; g++) {
        float m = NEGINF;
        for (int s = tid; s < NS; s += 256) m = fmaxf(m, sattn[g][s]);
        m = warp_max(m);
        if (lane == 0) sred[warp] = m;
        __syncthreads();
        if (tid == 0) {
            float mm = sred[0];
#pragma unroll
            for (int i = 1; i < 8; i++) mm = fmaxf(mm, sred[i]);
            sred[0] = mm;
        }
        __syncthreads();
        float bm = sred[0];
        __syncthreads();
        float sum = 0.f;
        for (int s = tid; s < NS; s += 256) {
            float e = __expf(sattn[g][s] - bm);
            sattn[g][s] = e;
            sum += e;
        }
        sum = warp_sum(sum);
        if (lane == 0) sred[warp] = sum;
        __syncthreads();
        if (tid == 0) {
            float t = 0.f;
#pragma unroll
            for (int i = 0; i < 8; i++) t += sred[i];
            sred[0] = t;
        }
        __syncthreads();
        float inv = 1.0f / sred[0];
        __syncthreads();
        int t_head = n * NG + g;
        for (int s = tid; s < NS; s += 256) {
            float a = sattn[g][s] * inv;
            sattn[g][s] = a;
            wout[((size_t)(b * NT + t_head)) * NS + s] = a;
        }
        __syncthreads();
    }

    // ---- Phase C: ah[g][e] = sum_s attn[g][s] * hist[b,s,e]
    for (int d = tid; d < ND; d += 256) {
        float c0 = 0.f, c1 = 0.f;
#pragma unroll 4
        for (int s = 0; s < NS; s++) {
            float h = hb[(size_t)s * ND + d];
            c0 += sattn[0][s] * h;
            c1 += sattn[1][s] * h;
        }
        sah[0][d] = c0;
        sah[1][d] = c1;
    }
    __syncthreads();

    // ---- Phase D: tokens[g][d] = sum_e ah[g][e] * Wv[n*512+d, e]
    const float* Wvn = Wv + (size_t)(n * ND) * ND;
    for (int d = warp; d < ND; d += 8) {
        const float* wr = Wvn + (size_t)d * ND;
        float c0 = 0.f, c1 = 0.f;
#pragma unroll
        for (int j = 0; j < 16; j++) {
            int e = lane + 32 * j;
            float w = wr[e];
            c0 += w * sah[0][e];
            c1 += w * sah[1][e];
        }
        c0 = warp_sum(c0);
        c1 = warp_sum(c1);
        if (lane == 0) {
            out[((size_t)(b * NT + n * NG + 0)) * ND + d] = c0;
            out[((size_t)(b * NT + n * NG + 1)) * ND + d] = c1;
        }
    }
}

// =====================================================================
extern "C" void kernel_launch(void* const* d_in, const int* in_sizes, int n_in,
                              void* d_out, int out_size) {
    const float* target = (const float*)d_in[0];
    const float* hist   = (const float*)d_in[1];
    const unsigned int* mask = (const unsigned int*)d_in[2];
    const float* wq  = (const float*)d_in[3];
    const float* wk  = (const float*)d_in[4];
    const float* wv  = (const float*)d_in[5];
    const float* qnw = (const float*)d_in[6];
    const float* knw = (const float*)d_in[7];
    float* out = (float*)d_out;

    q_kernel<<<NB * NT, 256>>>(target, wq, qnw, knw);
    qw_kernel<<<NB * NKV, 256>>>(wk);
    knorm_gemm<<<dim3(2048 / BN, 32768 / BM), 256>>>(hist, wk);
    rnorm_fin<<<(NB * NS * NKV) / 256, 256>>>();
    attn_kernel<<<NB * NKV, 256>>>(hist, mask, wv, out);
}

// round 6
// speedup vs baseline: 2.9699x; 2.9699x over previous
#include <cuda_runtime.h>
#include <cuda_bf16.h>
#include <cstdint>

#define NB 64
#define NT 8
#define ND 512
#define NS 512
#define NKV 4
#define NG 2
#define EPSV 1e-6f
#define SCALEV 0.04419417382415922f  /* 512^-0.5 */

#define NROWS (NB * NS)       /* 32768 */
#define KAUG 1536             /* [hi | hi | lo] augmented K */

// ---------------- scratch (device globals; no allocations) ----------------
__device__ float g_qprime[NB * NT * ND];
__device__ float g_qW[NB * NKV * NG * ND];
__device__ float g_part[NROWS * NKV * 4];              // [row][head][sub(4)]
__device__ float g_rnorm[NB * NS * NKV];
__device__ __nv_bfloat16 g_Ha[(size_t)NROWS * KAUG];   // 96 MB: [hist_hi | hist_hi | hist_lo]
__device__ __nv_bfloat16 g_Wb[(size_t)2048 * KAUG];    // 6 MB:  [Wk_hi | Wk_lo | Wk_hi]

// ---------------- helpers ----------------
__device__ __forceinline__ uint32_t smem_u32(const void* p) {
    uint32_t a;
    asm("{ .reg .u64 t; cvta.to.shared.u64 t, %1; cvt.u32.u64 %0, t; }" : "=r"(a) : "l"(p));
    return a;
}
__device__ __forceinline__ void cp16(uint32_t sm, const void* g) {
    asm volatile("cp.async.cg.shared.global [%0], [%1], 16;" :: "r"(sm), "l"(g));
}
#define CP_COMMIT() asm volatile("cp.async.commit_group;" ::: "memory")
#define CP_WAIT2()  asm volatile("cp.async.wait_group 2;" ::: "memory")

__device__ __forceinline__ void ldmx4(uint32_t a, uint32_t& r0, uint32_t& r1,
                                      uint32_t& r2, uint32_t& r3) {
    asm volatile("ldmatrix.sync.aligned.m8n8.x4.shared.b16 {%0,%1,%2,%3}, [%4];"
                 : "=r"(r0), "=r"(r1), "=r"(r2), "=r"(r3) : "r"(a));
}
__device__ __forceinline__ void mma16816(float* c, const uint32_t* a,
                                         uint32_t b0, uint32_t b1) {
    asm volatile(
        "mma.sync.aligned.m16n8k16.row.col.f32.bf16.bf16.f32 "
        "{%0,%1,%2,%3}, {%4,%5,%6,%7}, {%8,%9}, {%0,%1,%2,%3};"
        : "+f"(c[0]), "+f"(c[1]), "+f"(c[2]), "+f"(c[3])
        : "r"(a[0]), "r"(a[1]), "r"(a[2]), "r"(a[3]), "r"(b0), "r"(b1));
}
__device__ __forceinline__ float warp_sum(float v) {
#pragma unroll
    for (int o = 16; o; o >>= 1) v += __shfl_xor_sync(0xffffffffu, v, o);
    return v;
}
__device__ __forceinline__ float warp_max(float v) {
#pragma unroll
    for (int o = 16; o; o >>= 1) v = fmaxf(v, __shfl_xor_sync(0xffffffffu, v, o));
    return v;
}

// =====================================================================
// Conversion: fp32 -> 2-term bf16 split, K-augmented layout.
// =====================================================================
__device__ __forceinline__ void split4(float4 x, unsigned& h01, unsigned& h23,
                                       unsigned& l01, unsigned& l23) {
    float xs[4] = {x.x, x.y, x.z, x.w};
    unsigned short h[4], l[4];
#pragma unroll
    for (int j = 0; j < 4; j++) {
        __nv_bfloat16 hb = __float2bfloat16(xs[j]);
        __nv_bfloat16 lb = __float2bfloat16(xs[j] - __bfloat162float(hb));
        h[j] = __bfloat16_as_ushort(hb);
        l[j] = __bfloat16_as_ushort(lb);
    }
    h01 = ((unsigned)h[1] << 16) | h[0];
    h23 = ((unsigned)h[3] << 16) | h[2];
    l01 = ((unsigned)l[1] << 16) | l[0];
    l23 = ((unsigned)l[3] << 16) | l[2];
}

__global__ __launch_bounds__(256) void conv_h(const float* __restrict__ H) {
    int i = blockIdx.x * 256 + threadIdx.x;
    float4 x = ((const float4*)H)[i];
    int row = i >> 7;
    int col = (i & 127) * 4;
    unsigned h01, h23, l01, l23;
    split4(x, h01, h23, l01, l23);
    size_t rb = (size_t)row * KAUG;
    *(uint2*)&g_Ha[rb + col]        = make_uint2(h01, h23);
    *(uint2*)&g_Ha[rb + 512 + col]  = make_uint2(h01, h23);
    *(uint2*)&g_Ha[rb + 1024 + col] = make_uint2(l01, l23);
}

__global__ __launch_bounds__(256) void conv_w(const float* __restrict__ W) {
    int i = blockIdx.x * 256 + threadIdx.x;
    float4 x = ((const float4*)W)[i];
    int row = i >> 7;
    int col = (i & 127) * 4;
    unsigned h01, h23, l01, l23;
    split4(x, h01, h23, l01, l23);
    size_t rb = (size_t)row * KAUG;
    *(uint2*)&g_Wb[rb + col]        = make_uint2(h01, h23);
    *(uint2*)&g_Wb[rb + 512 + col]  = make_uint2(l01, l23);
    *(uint2*)&g_Wb[rb + 1024 + col] = make_uint2(h01, h23);
}

// =====================================================================
// knorm_mma: bf16 mma.sync GEMM + row-sumsq epilogue.
// C = A[32768 x 1536] @ B^T[2048 x 1536]; only row sumsq per 128-col tile kept.
// CTA 128x128, BK=32, 4-stage cp.async. Warp grid 2(m) x 4(n), warp tile 64x32.
// grid = (16, 256), 256 threads, 2 CTAs/SM.
// =====================================================================
#define BKB 32
#define RSTR 80                      /* smem row stride bytes: (32+8) bf16 */
#define TILE_A_B (128 * RSTR)        /* 10240 */
#define STAGE_B (2 * TILE_A_B)       /* 20480 */
#define NSTAGE 4
#define KSTEPS (KAUG / BKB)          /* 48 */

__global__ __launch_bounds__(256, 2) void knorm_mma() {
    extern __shared__ char dsm[];
    uint32_t sbase = smem_u32(dsm);

    int tid = threadIdx.x, lane = tid & 31, wid = tid >> 5;
    int wm = wid & 1, wn = wid >> 1;
    int bm = blockIdx.y * 128;
    int bn = blockIdx.x * 128;

    // ---- stage loader ----
    int lr = tid >> 2, lq = tid & 3;   // lr 0..63, lq 0..3 (16B chunk)
    auto load_stage = [&](int kt, int s) {
        uint32_t sb = sbase + s * STAGE_B;
#pragma unroll
        for (int i = 0; i < 2; i++) {
            int row = lr + i * 64;
            const __nv_bfloat16* g = g_Ha + (size_t)(bm + row) * KAUG + kt * BKB + lq * 8;
            cp16(sb + row * RSTR + lq * 16, g);
        }
#pragma unroll
        for (int i = 0; i < 2; i++) {
            int row = lr + i * 64;
            const __nv_bfloat16* g = g_Wb + (size_t)(bn + row) * KAUG + kt * BKB + lq * 8;
            cp16(sb + TILE_A_B + row * RSTR + lq * 16, g);
        }
        CP_COMMIT();
    };

    load_stage(0, 0);
    load_stage(1, 1);
    load_stage(2, 2);

    float c[4][4][4];
#pragma unroll
    for (int mt = 0; mt < 4; mt++)
#pragma unroll
        for (int nt = 0; nt < 4; nt++)
#pragma unroll
            for (int t = 0; t < 4; t++) c[mt][nt][t] = 0.f;

    // precomputed ldmatrix lane offsets
    int a_row = lane & 15, a_colb = (lane >> 4) * 16;
    int bg = lane >> 3;
    int b_row = (bg >> 1) * 8 + (lane & 7), b_colb = (bg & 1) * 16;

#pragma unroll 1
    for (int kt = 0; kt < KSTEPS; kt++) {
        int s = kt & 3;
        CP_WAIT2();
        __syncthreads();
        if (kt + 3 < KSTEPS) load_stage(kt + 3, (kt + 3) & 3);
        else CP_COMMIT();

        uint32_t sA = sbase + s * STAGE_B;
        uint32_t sB = sA + TILE_A_B;
#pragma unroll
        for (int ks = 0; ks < 2; ks++) {
            uint32_t af[4][4];
#pragma unroll
            for (int mt = 0; mt < 4; mt++) {
                uint32_t addr = sA + (wm * 64 + mt * 16 + a_row) * RSTR + ks * 32 + a_colb;
                ldmx4(addr, af[mt][0], af[mt][1], af[mt][2], af[mt][3]);
            }
            uint32_t bf[2][4];
#pragma unroll
            for (int nt2 = 0; nt2 < 2; nt2++) {
                uint32_t addr = sB + (wn * 32 + nt2 * 16 + b_row) * RSTR + ks * 32 + b_colb;
                ldmx4(addr, bf[nt2][0], bf[nt2][1], bf[nt2][2], bf[nt2][3]);
            }
#pragma unroll
            for (int mt = 0; mt < 4; mt++)
#pragma unroll
                for (int nt = 0; nt < 4; nt++)
                    mma16816(c[mt][nt], af[mt],
                             bf[nt >> 1][(nt & 1) * 2 + 0],
                             bf[nt >> 1][(nt & 1) * 2 + 1]);
        }
    }

    // ---- epilogue: per-row sumsq over this CTA's 128 cols ----
    __syncthreads();                      // stages dead; reuse smem for reduction
    float* red = (float*)dsm;             // [4][128]

    float ssA[4], ssB[4];
#pragma unroll
    for (int mt = 0; mt < 4; mt++) {
        float a = 0.f, b = 0.f;
#pragma unroll
        for (int nt = 0; nt < 4; nt++) {
            a += c[mt][nt][0] * c[mt][nt][0] + c[mt][nt][1] * c[mt][nt][1];
            b += c[mt][nt][2] * c[mt][nt][2] + c[mt][nt][3] * c[mt][nt][3];
        }
        // reduce over the 4 lanes covering the same rows (lane bits 0-1)
        a += __shfl_xor_sync(0xffffffffu, a, 1);
        a += __shfl_xor_sync(0xffffffffu, a, 2);
        b += __shfl_xor_sync(0xffffffffu, b, 1);
        b += __shfl_xor_sync(0xffffffffu, b, 2);
        ssA[mt] = a; ssB[mt] = b;
    }
    if ((lane & 3) == 0) {
        int r0 = wm * 64 + (lane >> 2);
#pragma unroll
        for (int mt = 0; mt < 4; mt++) {
            red[wn * 128 + r0 + mt * 16] = ssA[mt];
            red[wn * 128 + r0 + mt * 16 + 8] = ssB[mt];
        }
    }
    __syncthreads();
    if (tid < 128) {
        float s = red[tid] + red[128 + tid] + red[256 + tid] + red[384 + tid];
        int row = bm + tid;
        int head = blockIdx.x >> 2, sub = blockIdx.x & 3;
        g_part[((size_t)row * NKV + head) * 4 + sub] = s;
    }
}

// =====================================================================
// Kernel 1: q = rmsnorm(target @ Wq^T, qw) * (1+kw)
// =====================================================================
__global__ __launch_bounds__(256) void q_kernel(
    const float* __restrict__ tgt, const float* __restrict__ Wq,
    const float* __restrict__ qnw, const float* __restrict__ knw) {
    __shared__ float sx[ND];
    __shared__ float srow[ND];
    __shared__ float sred[8];
    int r = blockIdx.x;
    int tid = threadIdx.x, warp = tid >> 5, lane = tid & 31;

    for (int d = tid; d < ND; d += 256) sx[d] = tgt[r * ND + d];
    __syncthreads();

    for (int e = warp; e < ND; e += 8) {
        const float* wr = Wq + e * ND;
        float c = 0.f;
#pragma unroll
        for (int j = 0; j < 16; j++) {
            int d = lane + 32 * j;
            c += sx[d] * wr[d];
        }
        c = warp_sum(c);
        if (lane == 0) srow[e] = c;
    }
    __syncthreads();

    float ss = 0.f;
    for (int d = tid; d < ND; d += 256) { float v = srow[d]; ss += v * v; }
    ss = warp_sum(ss);
    if (lane == 0) sred[warp] = ss;
    __syncthreads();
    if (tid == 0) {
        float t = 0.f;
#pragma unroll
        for (int i = 0; i < 8; i++) t += sred[i];
        sred[0] = rsqrtf(t * (1.0f / ND) + EPSV);
    }
    __syncthreads();
    float rn = sred[0];
    for (int d = tid; d < ND; d += 256)
        g_qprime[r * ND + d] = srow[d] * rn * (1.f + qnw[d]) * (1.f + knw[d]);
}

// =====================================================================
// Kernel 2: qW[b,n,g,:] = q'[b, n*G+g, :] @ Wk_n
// =====================================================================
__global__ __launch_bounds__(256) void qw_kernel(const float* __restrict__ Wk) {
    __shared__ float sq[2][ND];
    int b = blockIdx.x >> 2, n = blockIdx.x & 3;
    int tid = threadIdx.x;
    for (int g = 0; g < 2; g++)
        for (int d = tid; d < ND; d += 256)
            sq[g][d] = g_qprime[((b * NT) + n * NG + g) * ND + d];
    __syncthreads();

    float c00 = 0.f, c01 = 0.f, c10 = 0.f, c11 = 0.f;
    const float* wb = Wk + (size_t)(n * ND) * ND;
#pragma unroll 4
    for (int d = 0; d < ND; d++) {
        float w0 = wb[(size_t)d * ND + tid];
        float w1 = wb[(size_t)d * ND + tid + 256];
        float s0 = sq[0][d], s1 = sq[1][d];
        c00 += s0 * w0; c01 += s0 * w1;
        c10 += s1 * w0; c11 += s1 * w1;
    }
    size_t base = ((size_t)(b * NKV + n) * NG) * ND;
    g_qW[base + tid] = c00; g_qW[base + tid + 256] = c01;
    g_qW[base + ND + tid] = c10; g_qW[base + ND + tid + 256] = c11;
}

// =====================================================================
// Kernel 4: finalize rnorm = rsqrt(mean + eps)
// =====================================================================
__global__ void rnorm_fin() {
    int i = blockIdx.x * 256 + threadIdx.x;  // row*NKV+head
    float s = g_part[i * 4 + 0] + g_part[i * 4 + 1] +
              g_part[i * 4 + 2] + g_part[i * 4 + 3];
    g_rnorm[i] = rsqrtf(s * (1.0f / ND) + EPSV);
}

// =====================================================================
// Kernel 5: attention per (b,n). mask read as 4-byte words.
// =====================================================================
__global__ __launch_bounds__(256) void attn_kernel(
    const float* __restrict__ hist, const unsigned int* __restrict__ mask,
    const float* __restrict__ Wv, float* __restrict__ out) {
    __shared__ float sqW[2][ND];
    __shared__ float sattn[2][NS];
    __shared__ float sah[2][ND];
    __shared__ float sred[8];

    int b = blockIdx.x >> 2, n = blockIdx.x & 3;
    int tid = threadIdx.x, warp = tid >> 5, lane = tid & 31;
    const float NEGINF = __int_as_float(0xff800000);

    size_t qbase = ((size_t)(b * NKV + n) * NG) * ND;
    for (int g = 0; g < 2; g++)
        for (int e = tid; e < ND; e += 256) sqW[g][e] = g_qW[qbase + g * ND + e];
    __syncthreads();

    const float* hb = hist + (size_t)b * NS * ND;
    for (int s = warp; s < NS; s += 8) {
        const float* hrow = hb + (size_t)s * ND;
        float a0 = 0.f, a1 = 0.f;
#pragma unroll
        for (int j = 0; j < 16; j++) {
            int d = lane + 32 * j;
            float h = hrow[d];
            a0 += h * sqW[0][d];
            a1 += h * sqW[1][d];
        }
        a0 = warp_sum(a0);
        a1 = warp_sum(a1);
        if (lane == 0) {
            float rn = g_rnorm[((size_t)b * NS + s) * NKV + n];
            float bias = (mask[b * NS + s] != 0u) ? NEGINF : 0.f;
            sattn[0][s] = a0 * rn * SCALEV + bias;
            sattn[1][s] = a1 * rn * SCALEV + bias;
        }
    }
    __syncthreads();

    float* wout = out + (size_t)NB * NT * ND;
    for (int g = 0; g < 2; g++) {
        float m = NEGINF;
        for (int s = tid; s < NS; s += 256) m = fmaxf(m, sattn[g][s]);
        m = warp_max(m);
        if (lane == 0) sred[warp] = m;
        __syncthreads();
        if (tid == 0) {
            float mm = sred[0];
#pragma unroll
            for (int i = 1; i < 8; i++) mm = fmaxf(mm, sred[i]);
            sred[0] = mm;
        }
        __syncthreads();
        float bm = sred[0];
        __syncthreads();
        float sum = 0.f;
        for (int s = tid; s < NS; s += 256) {
            float e = __expf(sattn[g][s] - bm);
            sattn[g][s] = e;
            sum += e;
        }
        sum = warp_sum(sum);
        if (lane == 0) sred[warp] = sum;
        __syncthreads();
        if (tid == 0) {
            float t = 0.f;
#pragma unroll
            for (int i = 0; i < 8; i++) t += sred[i];
            sred[0] = t;
        }
        __syncthreads();
        float inv = 1.0f / sred[0];
        __syncthreads();
        int t_head = n * NG + g;
        for (int s = tid; s < NS; s += 256) {
            float a = sattn[g][s] * inv;
            sattn[g][s] = a;
            wout[((size_t)(b * NT + t_head)) * NS + s] = a;
        }
        __syncthreads();
    }

    for (int d = tid; d < ND; d += 256) {
        float c0 = 0.f, c1 = 0.f;
#pragma unroll 4
        for (int s = 0; s < NS; s++) {
            float h = hb[(size_t)s * ND + d];
            c0 += sattn[0][s] * h;
            c1 += sattn[1][s] * h;
        }
        sah[0][d] = c0;
        sah[1][d] = c1;
    }
    __syncthreads();

    const float* Wvn = Wv + (size_t)(n * ND) * ND;
    for (int d = warp; d < ND; d += 8) {
        const float* wr = Wvn + (size_t)d * ND;
        float c0 = 0.f, c1 = 0.f;
#pragma unroll
        for (int j = 0; j < 16; j++) {
            int e = lane + 32 * j;
            float w = wr[e];
            c0 += w * sah[0][e];
            c1 += w * sah[1][e];
        }
        c0 = warp_sum(c0);
        c1 = warp_sum(c1);
        if (lane == 0) {
            out[((size_t)(b * NT + n * NG + 0)) * ND + d] = c0;
            out[((size_t)(b * NT + n * NG + 1)) * ND + d] = c1;
        }
    }
}

// =====================================================================
extern "C" void kernel_launch(void* const* d_in, const int* in_sizes, int n_in,
                              void* d_out, int out_size) {
    const float* target = (const float*)d_in[0];
    const float* hist   = (const float*)d_in[1];
    const unsigned int* mask = (const unsigned int*)d_in[2];
    const float* wq  = (const float*)d_in[3];
    const float* wk  = (const float*)d_in[4];
    const float* wv  = (const float*)d_in[5];
    const float* qnw = (const float*)d_in[6];
    const float* knw = (const float*)d_in[7];
    float* out = (float*)d_out;

    const int SMEM = NSTAGE * STAGE_B;   // 81920
    cudaFuncSetAttribute(knorm_mma, cudaFuncAttributeMaxDynamicSharedMemorySize, SMEM);

    conv_h<<<NROWS * ND / 4 / 256, 256>>>(hist);
    conv_w<<<2048 * ND / 4 / 256, 256>>>(wk);
    q_kernel<<<NB * NT, 256>>>(target, wq, qnw, knw);
    qw_kernel<<<NB * NKV, 256>>>(wk);
    knorm_mma<<<dim3(16, 256), 256, SMEM>>>();
    rnorm_fin<<<(NB * NS * NKV) / 256, 256>>>();
    attn_kernel<<<NB * NKV, 256>>>(hist, mask, wv, out);
}

// round 9
// speedup vs baseline: 6.4145x; 2.1598x over previous
#include <cuda_runtime.h>
#include <cuda_bf16.h>
#include <cstdint>

#define NB 64
#define NT 8
#define ND 512
#define NS 512
#define NKV 4
#define NG 2
#define EPSV 1e-6f
#define SCALEV 0.04419417382415922f  /* 512^-0.5 */

#define NROWS (NB * NS)       /* 32768 */

// ---------------- scratch (device globals; no allocations) ----------------
__device__ float g_qtmp[NB * NT * ND];                 // raw q projection
__device__ float g_qprime[NB * NT * ND];               // rms-normed * (1+qw)(1+kw)
__device__ float g_qW[NB * NT * ND];                   // row t = b*8+n*2+g
__device__ float g_ah[NB * NT * ND];                   // attn @ hist
__device__ float g_part[NROWS * NKV * 4];              // [row][head][sub(4)]
__device__ float g_rnorm[NB * NS * NKV];
__device__ __nv_bfloat16 g_Ha[(size_t)NROWS * ND];     // 32 MB: hist hi
__device__ __nv_bfloat16 g_Wb[(size_t)2048 * ND];      // 2 MB:  Wk hi

// ---------------- helpers ----------------
__device__ __forceinline__ uint32_t smem_u32(const void* p) {
    uint32_t a;
    asm("{ .reg .u64 t; cvta.to.shared.u64 t, %1; cvt.u32.u64 %0, t; }" : "=r"(a) : "l"(p));
    return a;
}
__device__ __forceinline__ void cp16(uint32_t sm, const void* g) {
    asm volatile("cp.async.cg.shared.global [%0], [%1], 16;" :: "r"(sm), "l"(g));
}
#define CP_COMMIT() asm volatile("cp.async.commit_group;" ::: "memory")
#define CP_WAIT2()  asm volatile("cp.async.wait_group 2;" ::: "memory")

__device__ __forceinline__ void ldmx4(uint32_t a, uint32_t& r0, uint32_t& r1,
                                      uint32_t& r2, uint32_t& r3) {
    asm volatile("ldmatrix.sync.aligned.m8n8.x4.shared.b16 {%0,%1,%2,%3}, [%4];"
                 : "=r"(r0), "=r"(r1), "=r"(r2), "=r"(r3) : "r"(a));
}
__device__ __forceinline__ void mma16816(float* c, const uint32_t* a,
                                         uint32_t b0, uint32_t b1) {
    asm volatile(
        "mma.sync.aligned.m16n8k16.row.col.f32.bf16.bf16.f32 "
        "{%0,%1,%2,%3}, {%4,%5,%6,%7}, {%8,%9}, {%0,%1,%2,%3};"
        : "+f"(c[0]), "+f"(c[1]), "+f"(c[2]), "+f"(c[3])
        : "r"(a[0]), "r"(a[1]), "r"(a[2]), "r"(a[3]), "r"(b0), "r"(b1));
}
__device__ __forceinline__ float warp_sum(float v) {
#pragma unroll
    for (int o = 16; o; o >>= 1) v += __shfl_xor_sync(0xffffffffu, v, o);
    return v;
}
__device__ __forceinline__ float warp_max(float v) {
#pragma unroll
    for (int o = 16; o; o >>= 1) v = fmaxf(v, __shfl_xor_sync(0xffffffffu, v, o));
    return v;
}

// =====================================================================
// Conversion: fp32 -> bf16 (hi only)
// =====================================================================
__global__ __launch_bounds__(256) void conv_h(const float* __restrict__ H) {
    int i = blockIdx.x * 256 + threadIdx.x;
    float4 x = ((const float4*)H)[i];
    unsigned short h0 = __bfloat16_as_ushort(__float2bfloat16(x.x));
    unsigned short h1 = __bfloat16_as_ushort(__float2bfloat16(x.y));
    unsigned short h2 = __bfloat16_as_ushort(__float2bfloat16(x.z));
    unsigned short h3 = __bfloat16_as_ushort(__float2bfloat16(x.w));
    *(uint2*)&g_Ha[(size_t)i * 4] =
        make_uint2(((unsigned)h1 << 16) | h0, ((unsigned)h3 << 16) | h2);
}
__global__ __launch_bounds__(256) void conv_w(const float* __restrict__ W) {
    int i = blockIdx.x * 256 + threadIdx.x;
    float4 x = ((const float4*)W)[i];
    unsigned short h0 = __bfloat16_as_ushort(__float2bfloat16(x.x));
    unsigned short h1 = __bfloat16_as_ushort(__float2bfloat16(x.y));
    unsigned short h2 = __bfloat16_as_ushort(__float2bfloat16(x.z));
    unsigned short h3 = __bfloat16_as_ushort(__float2bfloat16(x.w));
    *(uint2*)&g_Wb[(size_t)i * 4] =
        make_uint2(((unsigned)h1 << 16) | h0, ((unsigned)h3 << 16) | h2);
}

// =====================================================================
// Tiled fp32 SGEMM (64x64, BK=16): C[r][e] = sum_d A[r][d] * B[e][d]
// =====================================================================
__device__ __forceinline__ void sgemm_tile_body(
    const float* __restrict__ A, const float* __restrict__ B,
    int a_row0, int b_row0, float c[4][4]) {
    __shared__ float As[16][68];
    __shared__ float Bs[16][68];
    int tid = threadIdx.x;
    int r = tid >> 2, q4 = (tid & 3) * 4;
    int ty = tid >> 4, tx = tid & 15;
#pragma unroll 1
    for (int kt = 0; kt < 32; kt++) {
        float4 a = *(const float4*)&A[(size_t)(a_row0 + r) * 512 + kt * 16 + q4];
        float4 b = *(const float4*)&B[(size_t)(b_row0 + r) * 512 + kt * 16 + q4];
        As[q4 + 0][r] = a.x; As[q4 + 1][r] = a.y; As[q4 + 2][r] = a.z; As[q4 + 3][r] = a.w;
        Bs[q4 + 0][r] = b.x; Bs[q4 + 1][r] = b.y; Bs[q4 + 2][r] = b.z; Bs[q4 + 3][r] = b.w;
        __syncthreads();
#pragma unroll
        for (int k = 0; k < 16; k++) {
            float av[4], bv[4];
#pragma unroll
            for (int i = 0; i < 4; i++) av[i] = As[k][ty * 4 + i];
#pragma unroll
            for (int j = 0; j < 4; j++) bv[j] = Bs[k][tx * 4 + j];
#pragma unroll
            for (int i = 0; i < 4; i++)
#pragma unroll
                for (int j = 0; j < 4; j++) c[i][j] += av[i] * bv[j];
        }
        __syncthreads();
    }
}

// dense: C[512x512] = A @ B^T  (q projection). grid (8, 8)
__global__ __launch_bounds__(256) void gemm_q(
    const float* __restrict__ A, const float* __restrict__ B) {
    float c[4][4] = {};
    int bm = blockIdx.y * 64, bn = blockIdx.x * 64;
    sgemm_tile_body(A, B, bm, bn, c);
    int ty = threadIdx.x >> 4, tx = threadIdx.x & 15;
#pragma unroll
    for (int i = 0; i < 4; i++)
#pragma unroll
        for (int j = 0; j < 4; j++)
            g_qtmp[(size_t)(bm + ty * 4 + i) * 512 + bn + tx * 4 + j] = c[i][j];
}

// =====================================================================
// gemm_qw (TRANSPOSED-B): qW[row][d] = sum_e q'[row][e] * Wk[n*512+e][d]
// Contraction over Wk ROWS (head-n output dim e); result indexed by Wk col d.
// Rows gathered: local row lr -> global (lr>>1)*8 + n*2 + (lr&1).
// grid (8 dtiles, 2 mtiles, 4 heads), 256 threads.
// =====================================================================
__global__ __launch_bounds__(256) void gemm_qw(const float* __restrict__ Wk) {
    __shared__ float As[16][68];
    __shared__ float Bs[16][68];
    int tid = threadIdx.x;
    int n = blockIdx.z;
    int bm = blockIdx.y * 64, bn = blockIdx.x * 64;
    int r = tid >> 2, q4 = (tid & 3) * 4;       // A load (gathered rows)
    int krow = tid >> 4, c4 = (tid & 15) * 4;   // B load (along Wk rows)
    int ty = tid >> 4, tx = tid & 15;
    float c[4][4] = {};
    int lr = bm + r;
    int grow_r = (lr >> 1) * 8 + n * 2 + (lr & 1);
#pragma unroll 1
    for (int kt = 0; kt < 32; kt++) {
        float4 a = *(const float4*)&g_qprime[(size_t)grow_r * 512 + kt * 16 + q4];
        As[q4 + 0][r] = a.x; As[q4 + 1][r] = a.y; As[q4 + 2][r] = a.z; As[q4 + 3][r] = a.w;
        float4 b = *(const float4*)&Wk[(size_t)(n * 512 + kt * 16 + krow) * 512 + bn + c4];
        Bs[krow][c4 + 0] = b.x; Bs[krow][c4 + 1] = b.y;
        Bs[krow][c4 + 2] = b.z; Bs[krow][c4 + 3] = b.w;
        __syncthreads();
#pragma unroll
        for (int k = 0; k < 16; k++) {
            float av[4], bv[4];
#pragma unroll
            for (int i = 0; i < 4; i++) av[i] = As[k][ty * 4 + i];
#pragma unroll
            for (int j = 0; j < 4; j++) bv[j] = Bs[k][tx * 4 + j];
#pragma unroll
            for (int i = 0; i < 4; i++)
#pragma unroll
                for (int j = 0; j < 4; j++) c[i][j] += av[i] * bv[j];
        }
        __syncthreads();
    }
#pragma unroll
    for (int i = 0; i < 4; i++) {
        int lrow = bm + ty * 4 + i;
        int grow = (lrow >> 1) * 8 + n * 2 + (lrow & 1);
#pragma unroll
        for (int j = 0; j < 4; j++)
            g_qW[(size_t)grow * 512 + bn + tx * 4 + j] = c[i][j];
    }
}

// =====================================================================
// gemm_tok: tokens[row][d] = sum_e ah[row][e] * Wv[n*512+d][e]
// (contraction over Wv's SECOND index — B-transposed form is correct here)
// =====================================================================
__global__ __launch_bounds__(256) void gemm_tok(const float* __restrict__ Wv,
                                                float* __restrict__ out) {
    __shared__ float As[16][68];
    __shared__ float Bs[16][68];
    int tid = threadIdx.x;
    int n = blockIdx.z;
    int bm = blockIdx.y * 64, bn = blockIdx.x * 64;
    int r = tid >> 2, q4 = (tid & 3) * 4;
    int ty = tid >> 4, tx = tid & 15;
    float c[4][4] = {};
    int lr = bm + r;
    int grow_r = (lr >> 1) * 8 + n * 2 + (lr & 1);
#pragma unroll 1
    for (int kt = 0; kt < 32; kt++) {
        float4 a = *(const float4*)&g_ah[(size_t)grow_r * 512 + kt * 16 + q4];
        float4 b = *(const float4*)&Wv[(size_t)(n * 512 + bn + r) * 512 + kt * 16 + q4];
        As[q4 + 0][r] = a.x; As[q4 + 1][r] = a.y; As[q4 + 2][r] = a.z; As[q4 + 3][r] = a.w;
        Bs[q4 + 0][r] = b.x; Bs[q4 + 1][r] = b.y; Bs[q4 + 2][r] = b.z; Bs[q4 + 3][r] = b.w;
        __syncthreads();
#pragma unroll
        for (int k = 0; k < 16; k++) {
            float av[4], bv[4];
#pragma unroll
            for (int i = 0; i < 4; i++) av[i] = As[k][ty * 4 + i];
#pragma unroll
            for (int j = 0; j < 4; j++) bv[j] = Bs[k][tx * 4 + j];
#pragma unroll
            for (int i = 0; i < 4; i++)
#pragma unroll
                for (int j = 0; j < 4; j++) c[i][j] += av[i] * bv[j];
        }
        __syncthreads();
    }
#pragma unroll
    for (int i = 0; i < 4; i++) {
        int lrow = bm + ty * 4 + i;
        int grow = (lrow >> 1) * 8 + n * 2 + (lrow & 1);
#pragma unroll
        for (int j = 0; j < 4; j++)
            out[(size_t)grow * 512 + bn + tx * 4 + j] = c[i][j];
    }
}

// =====================================================================
// rms_fold: g_qprime = rmsnorm(g_qtmp) * (1+qw)(1+kw). grid 512
// =====================================================================
__global__ __launch_bounds__(256) void rms_fold(
    const float* __restrict__ qnw, const float* __restrict__ knw) {
    __shared__ float sred[8];
    int r = blockIdx.x, tid = threadIdx.x, warp = tid >> 5, lane = tid & 31;
    float v0 = g_qtmp[(size_t)r * 512 + tid];
    float v1 = g_qtmp[(size_t)r * 512 + tid + 256];
    float ss = warp_sum(v0 * v0 + v1 * v1);
    if (lane == 0) sred[warp] = ss;
    __syncthreads();
    if (tid == 0) {
        float t = 0.f;
#pragma unroll
        for (int i = 0; i < 8; i++) t += sred[i];
        sred[0] = rsqrtf(t * (1.0f / ND) + EPSV);
    }
    __syncthreads();
    float rn = sred[0];
    g_qprime[(size_t)r * 512 + tid] = v0 * rn * (1.f + qnw[tid]) * (1.f + knw[tid]);
    g_qprime[(size_t)r * 512 + tid + 256] =
        v1 * rn * (1.f + qnw[tid + 256]) * (1.f + knw[tid + 256]);
}

// =====================================================================
// knorm_mma: bf16 mma.sync GEMM (hi-only, K=512) + row-sumsq epilogue.
// CTA 128x128, BK=32, 4-stage cp.async. grid (16, 256), 256 thr, 2 CTA/SM.
// =====================================================================
#define BKB 32
#define RSTR 80
#define TILE_A_B (128 * RSTR)
#define STAGE_B (2 * TILE_A_B)
#define NSTAGE 4
#define KSTEPS (ND / BKB)            /* 16 */

__global__ __launch_bounds__(256, 2) void knorm_mma() {
    extern __shared__ char dsm[];
    uint32_t sbase = smem_u32(dsm);

    int tid = threadIdx.x, lane = tid & 31, wid = tid >> 5;
    int wm = wid & 1, wn = wid >> 1;
    int bm = blockIdx.y * 128;
    int bn = blockIdx.x * 128;

    int lr = tid >> 2, lq = tid & 3;
    auto load_stage = [&](int kt, int s) {
        uint32_t sb = sbase + s * STAGE_B;
#pragma unroll
        for (int i = 0; i < 2; i++) {
            int row = lr + i * 64;
            const __nv_bfloat16* g = g_Ha + (size_t)(bm + row) * ND + kt * BKB + lq * 8;
            cp16(sb + row * RSTR + lq * 16, g);
        }
#pragma unroll
        for (int i = 0; i < 2; i++) {
            int row = lr + i * 64;
            const __nv_bfloat16* g = g_Wb + (size_t)(bn + row) * ND + kt * BKB + lq * 8;
            cp16(sb + TILE_A_B + row * RSTR + lq * 16, g);
        }
        CP_COMMIT();
    };

    load_stage(0, 0);
    load_stage(1, 1);
    load_stage(2, 2);

    float c[4][4][4];
#pragma unroll
    for (int mt = 0; mt < 4; mt++)
#pragma unroll
        for (int nt = 0; nt < 4; nt++)
#pragma unroll
            for (int t = 0; t < 4; t++) c[mt][nt][t] = 0.f;

    int a_row = lane & 15, a_colb = (lane >> 4) * 16;
    int bg = lane >> 3;
    int b_row = (bg >> 1) * 8 + (lane & 7), b_colb = (bg & 1) * 16;

#pragma unroll 1
    for (int kt = 0; kt < KSTEPS; kt++) {
        int s = kt & 3;
        CP_WAIT2();
        __syncthreads();
        if (kt + 3 < KSTEPS) load_stage(kt + 3, (kt + 3) & 3);
        else CP_COMMIT();

        uint32_t sA = sbase + s * STAGE_B;
        uint32_t sB = sA + TILE_A_B;
#pragma unroll
        for (int ks = 0; ks < 2; ks++) {
            uint32_t af[4][4];
#pragma unroll
            for (int mt = 0; mt < 4; mt++) {
                uint32_t addr = sA + (wm * 64 + mt * 16 + a_row) * RSTR + ks * 32 + a_colb;
                ldmx4(addr, af[mt][0], af[mt][1], af[mt][2], af[mt][3]);
            }
            uint32_t bf[2][4];
#pragma unroll
            for (int nt2 = 0; nt2 < 2; nt2++) {
                uint32_t addr = sB + (wn * 32 + nt2 * 16 + b_row) * RSTR + ks * 32 + b_colb;
                ldmx4(addr, bf[nt2][0], bf[nt2][1], bf[nt2][2], bf[nt2][3]);
            }
#pragma unroll
            for (int mt = 0; mt < 4; mt++)
#pragma unroll
                for (int nt = 0; nt < 4; nt++)
                    mma16816(c[mt][nt], af[mt],
                             bf[nt >> 1][(nt & 1) * 2 + 0],
                             bf[nt >> 1][(nt & 1) * 2 + 1]);
        }
    }

    // ---- epilogue: per-row sumsq over this CTA's 128 cols ----
    __syncthreads();
    float* red = (float*)dsm;

    float ssA[4], ssB[4];
#pragma unroll
    for (int mt = 0; mt < 4; mt++) {
        float a = 0.f, b = 0.f;
#pragma unroll
        for (int nt = 0; nt < 4; nt++) {
            a += c[mt][nt][0] * c[mt][nt][0] + c[mt][nt][1] * c[mt][nt][1];
            b += c[mt][nt][2] * c[mt][nt][2] + c[mt][nt][3] * c[mt][nt][3];
        }
        a += __shfl_xor_sync(0xffffffffu, a, 1);
        a += __shfl_xor_sync(0xffffffffu, a, 2);
        b += __shfl_xor_sync(0xffffffffu, b, 1);
        b += __shfl_xor_sync(0xffffffffu, b, 2);
        ssA[mt] = a; ssB[mt] = b;
    }
    if ((lane & 3) == 0) {
        int r0 = wm * 64 + (lane >> 2);
#pragma unroll
        for (int mt = 0; mt < 4; mt++) {
            red[wn * 128 + r0 + mt * 16] = ssA[mt];
            red[wn * 128 + r0 + mt * 16 + 8] = ssB[mt];
        }
    }
    __syncthreads();
    if (tid < 128) {
        float s = red[tid] + red[128 + tid] + red[256 + tid] + red[384 + tid];
        int row = bm + tid;
        int head = blockIdx.x >> 2, sub = blockIdx.x & 3;
        g_part[((size_t)row * NKV + head) * 4 + sub] = s;
    }
}

// =====================================================================
// rnorm_fin
// =====================================================================
__global__ void rnorm_fin() {
    int i = blockIdx.x * 256 + threadIdx.x;
    float s = g_part[i * 4 + 0] + g_part[i * 4 + 1] +
              g_part[i * 4 + 2] + g_part[i * 4 + 3];
    g_rnorm[i] = rsqrtf(s * (1.0f / ND) + EPSV);
}

// =====================================================================
// attn_kernel: one block per batch b, all 8 heads. 512 threads.
// =====================================================================
__global__ __launch_bounds__(512) void attn_kernel(
    const float* __restrict__ hist, const unsigned int* __restrict__ mask,
    float* __restrict__ out) {
    __shared__ float sqW[8][512];
    __shared__ float sattn[8][512];
    __shared__ float red[16];

    int b = blockIdx.x;
    int tid = threadIdx.x, warp = tid >> 5, lane = tid & 31;
    const float NEGINF = __int_as_float(0xff800000);

    for (int i = tid; i < 8 * 512; i += 512)
        ((float*)sqW)[i] = g_qW[(size_t)b * 4096 + i];
    __syncthreads();

    const float* hb = hist + (size_t)b * NS * ND;

    // ---- Phase A: scores ----
    for (int s = warp; s < NS; s += 16) {
        const float* hrow = hb + (size_t)s * ND;
        float acc[8] = {};
#pragma unroll
        for (int j = 0; j < 16; j++) {
            int d = lane + 32 * j;
            float h = hrow[d];
#pragma unroll
            for (int t = 0; t < 8; t++) acc[t] += h * sqW[t][d];
        }
#pragma unroll
        for (int t = 0; t < 8; t++) acc[t] = warp_sum(acc[t]);
        if (lane == 0) {
            float bias = (mask[b * NS + s] != 0u) ? NEGINF : 0.f;
#pragma unroll
            for (int t = 0; t < 8; t++) {
                float rn = g_rnorm[((size_t)b * NS + s) * NKV + (t >> 1)];
                sattn[t][s] = acc[t] * rn * SCALEV + bias;
            }
        }
    }
    __syncthreads();

    // ---- Phase B: softmax per head; thread owns key s = tid ----
    float* wout = out + (size_t)NB * NT * ND;
#pragma unroll 1
    for (int h = 0; h < 8; h++) {
        float v = sattn[h][tid];
        float m = warp_max(v);
        if (lane == 0) red[warp] = m;
        __syncthreads();
        if (tid == 0) {
            float mm = red[0];
#pragma unroll
            for (int i = 1; i < 16; i++) mm = fmaxf(mm, red[i]);
            red[0] = mm;
        }
        __syncthreads();
        float bm = red[0];
        __syncthreads();
        float e = __expf(v - bm);
        float sm = warp_sum(e);
        if (lane == 0) red[warp] = sm;
        __syncthreads();
        if (tid == 0) {
            float t = 0.f;
#pragma unroll
            for (int i = 0; i < 16; i++) t += red[i];
            red[0] = t;
        }
        __syncthreads();
        float a = e * (1.0f / red[0]);
        __syncthreads();
        sattn[h][tid] = a;
        wout[((size_t)(b * NT + h)) * NS + tid] = a;
    }
    __syncthreads();

    // ---- Phase C: g_ah[b*8+h][d] = sum_s attn[h][s] * hist[b,s,d] ----
    int d = tid;
    float c[8] = {};
#pragma unroll 4
    for (int s = 0; s < NS; s++) {
        float h = hb[(size_t)s * ND + d];
#pragma unroll
        for (int t = 0; t < 8; t++) c[t] += sattn[t][s] * h;
    }
#pragma unroll
    for (int t = 0; t < 8; t++)
        g_ah[((size_t)(b * NT + t)) * ND + d] = c[t];
}

// =====================================================================
extern "C" void kernel_launch(void* const* d_in, const int* in_sizes, int n_in,
                              void* d_out, int out_size) {
    const float* target = (const float*)d_in[0];
    const float* hist   = (const float*)d_in[1];
    const unsigned int* mask = (const unsigned int*)d_in[2];
    const float* wq  = (const float*)d_in[3];
    const float* wk  = (const float*)d_in[4];
    const float* wv  = (const float*)d_in[5];
    const float* qnw = (const float*)d_in[6];
    const float* knw = (const float*)d_in[7];
    float* out = (float*)d_out;

    const int SMEM = NSTAGE * STAGE_B;   // 81920
    cudaFuncSetAttribute(knorm_mma, cudaFuncAttributeMaxDynamicSharedMemorySize, SMEM);

    conv_h<<<NROWS * ND / 4 / 256, 256>>>(hist);
    conv_w<<<2048 * ND / 4 / 256, 256>>>(wk);
    gemm_q<<<dim3(8, 8), 256>>>(target, wq);
    rms_fold<<<NB * NT, 256>>>(qnw, knw);
    gemm_qw<<<dim3(8, 2, 4), 256>>>(wk);
    knorm_mma<<<dim3(16, 256), 256, SMEM>>>();
    rnorm_fin<<<(NB * NS * NKV) / 256, 256>>>();
    attn_kernel<<<NB, 512>>>(hist, mask, out);
    gemm_tok<<<dim3(8, 2, 4), 256>>>(wv, out);
}

// round 12
// speedup vs baseline: 6.5387x; 1.0194x over previous
#include <cuda_runtime.h>
#include <cuda_bf16.h>
#include <cstdint>

#define NB 64
#define NT 8
#define ND 512
#define NS 512
#define NKV 4
#define NG 2
#define EPSV 1e-6f
#define SCALEV 0.04419417382415922f  /* 512^-0.5 */

#define NROWS (NB * NS)       /* 32768 */

// ---------------- scratch (device globals; no allocations) ----------------
__device__ float g_qtmp[NB * NT * ND];
__device__ float g_qprime[NB * NT * ND];
__device__ float g_qW[NB * NT * ND];
__device__ float g_ah[NB * NT * ND];
__device__ float g_scores[NB * NT * NS];               // scores -> attn (in place)
__device__ float g_part[NROWS * NKV * 2];              // [row][head][sub(2)]
__device__ float g_rnorm[NB * NS * NKV];
__device__ __nv_bfloat16 g_Ha[(size_t)NROWS * ND];     // 32 MB: hist hi
__device__ __nv_bfloat16 g_Wb[(size_t)2048 * ND];      // 2 MB:  Wk hi

// ---------------- helpers ----------------
__device__ __forceinline__ uint32_t smem_u32(const void* p) {
    uint32_t a;
    asm("{ .reg .u64 t; cvta.to.shared.u64 t, %1; cvt.u32.u64 %0, t; }" : "=r"(a) : "l"(p));
    return a;
}
__device__ __forceinline__ void cp16(uint32_t sm, const void* g) {
    asm volatile("cp.async.cg.shared.global [%0], [%1], 16;" :: "r"(sm), "l"(g));
}
#define CP_COMMIT() asm volatile("cp.async.commit_group;" ::: "memory")
#define CP_WAIT1()  asm volatile("cp.async.wait_group 1;" ::: "memory")

__device__ __forceinline__ void ldmx4(uint32_t a, uint32_t& r0, uint32_t& r1,
                                      uint32_t& r2, uint32_t& r3) {
    asm volatile("ldmatrix.sync.aligned.m8n8.x4.shared.b16 {%0,%1,%2,%3}, [%4];"
                 : "=r"(r0), "=r"(r1), "=r"(r2), "=r"(r3) : "r"(a));
}
__device__ __forceinline__ void mma16816(float* c, const uint32_t* a,
                                         uint32_t b0, uint32_t b1) {
    asm volatile(
        "mma.sync.aligned.m16n8k16.row.col.f32.bf16.bf16.f32 "
        "{%0,%1,%2,%3}, {%4,%5,%6,%7}, {%8,%9}, {%0,%1,%2,%3};"
        : "+f"(c[0]), "+f"(c[1]), "+f"(c[2]), "+f"(c[3])
        : "r"(a[0]), "r"(a[1]), "r"(a[2]), "r"(a[3]), "r"(b0), "r"(b1));
}
__device__ __forceinline__ float warp_sum(float v) {
#pragma unroll
    for (int o = 16; o; o >>= 1) v += __shfl_xor_sync(0xffffffffu, v, o);
    return v;
}
__device__ __forceinline__ float warp_max(float v) {
#pragma unroll
    for (int o = 16; o; o >>= 1) v = fmaxf(v, __shfl_xor_sync(0xffffffffu, v, o));
    return v;
}

// =====================================================================
// Conversion: fp32 -> bf16 (hi only)
// =====================================================================
__global__ __launch_bounds__(256) void conv_h(const float* __restrict__ H) {
    int i = blockIdx.x * 256 + threadIdx.x;
    float4 x = ((const float4*)H)[i];
    unsigned short h0 = __bfloat16_as_ushort(__float2bfloat16(x.x));
    unsigned short h1 = __bfloat16_as_ushort(__float2bfloat16(x.y));
    unsigned short h2 = __bfloat16_as_ushort(__float2bfloat16(x.z));
    unsigned short h3 = __bfloat16_as_ushort(__float2bfloat16(x.w));
    *(uint2*)&g_Ha[(size_t)i * 4] =
        make_uint2(((unsigned)h1 << 16) | h0, ((unsigned)h3 << 16) | h2);
}
__global__ __launch_bounds__(256) void conv_w(const float* __restrict__ W) {
    int i = blockIdx.x * 256 + threadIdx.x;
    float4 x = ((const float4*)W)[i];
    unsigned short h0 = __bfloat16_as_ushort(__float2bfloat16(x.x));
    unsigned short h1 = __bfloat16_as_ushort(__float2bfloat16(x.y));
    unsigned short h2 = __bfloat16_as_ushort(__float2bfloat16(x.z));
    unsigned short h3 = __bfloat16_as_ushort(__float2bfloat16(x.w));
    *(uint2*)&g_Wb[(size_t)i * 4] =
        make_uint2(((unsigned)h1 << 16) | h0, ((unsigned)h3 << 16) | h2);
}

// =====================================================================
// Tiled fp32 SGEMM (64x64, BK=16): C[r][e] = sum_d A[r][d] * B[e][d]
// =====================================================================
__device__ __forceinline__ void sgemm_tile_body(
    const float* __restrict__ A, const float* __restrict__ B,
    int a_row0, int b_row0, float c[4][4]) {
    __shared__ float As[16][68];
    __shared__ float Bs[16][68];
    int tid = threadIdx.x;
    int r = tid >> 2, q4 = (tid & 3) * 4;
    int ty = tid >> 4, tx = tid & 15;
#pragma unroll 1
    for (int kt = 0; kt < 32; kt++) {
        float4 a = *(const float4*)&A[(size_t)(a_row0 + r) * 512 + kt * 16 + q4];
        float4 b = *(const float4*)&B[(size_t)(b_row0 + r) * 512 + kt * 16 + q4];
        As[q4 + 0][r] = a.x; As[q4 + 1][r] = a.y; As[q4 + 2][r] = a.z; As[q4 + 3][r] = a.w;
        Bs[q4 + 0][r] = b.x; Bs[q4 + 1][r] = b.y; Bs[q4 + 2][r] = b.z; Bs[q4 + 3][r] = b.w;
        __syncthreads();
#pragma unroll
        for (int k = 0; k < 16; k++) {
            float av[4], bv[4];
#pragma unroll
            for (int i = 0; i < 4; i++) av[i] = As[k][ty * 4 + i];
#pragma unroll
            for (int j = 0; j < 4; j++) bv[j] = Bs[k][tx * 4 + j];
#pragma unroll
            for (int i = 0; i < 4; i++)
#pragma unroll
                for (int j = 0; j < 4; j++) c[i][j] += av[i] * bv[j];
        }
        __syncthreads();
    }
}

__global__ __launch_bounds__(256) void gemm_q(
    const float* __restrict__ A, const float* __restrict__ B) {
    float c[4][4] = {};
    int bm = blockIdx.y * 64, bn = blockIdx.x * 64;
    sgemm_tile_body(A, B, bm, bn, c);
    int ty = threadIdx.x >> 4, tx = threadIdx.x & 15;
#pragma unroll
    for (int i = 0; i < 4; i++)
#pragma unroll
        for (int j = 0; j < 4; j++)
            g_qtmp[(size_t)(bm + ty * 4 + i) * 512 + bn + tx * 4 + j] = c[i][j];
}

// gemm_qw (TRANSPOSED-B): qW[row][d] = sum_e q'[row][e] * Wk[n*512+e][d]
__global__ __launch_bounds__(256) void gemm_qw(const float* __restrict__ Wk) {
    __shared__ float As[16][68];
    __shared__ float Bs[16][68];
    int tid = threadIdx.x;
    int n = blockIdx.z;
    int bm = blockIdx.y * 64, bn = blockIdx.x * 64;
    int r = tid >> 2, q4 = (tid & 3) * 4;
    int krow = tid >> 4, c4 = (tid & 15) * 4;
    int ty = tid >> 4, tx = tid & 15;
    float c[4][4] = {};
    int lr = bm + r;
    int grow_r = (lr >> 1) * 8 + n * 2 + (lr & 1);
#pragma unroll 1
    for (int kt = 0; kt < 32; kt++) {
        float4 a = *(const float4*)&g_qprime[(size_t)grow_r * 512 + kt * 16 + q4];
        As[q4 + 0][r] = a.x; As[q4 + 1][r] = a.y; As[q4 + 2][r] = a.z; As[q4 + 3][r] = a.w;
        float4 b = *(const float4*)&Wk[(size_t)(n * 512 + kt * 16 + krow) * 512 + bn + c4];
        Bs[krow][c4 + 0] = b.x; Bs[krow][c4 + 1] = b.y;
        Bs[krow][c4 + 2] = b.z; Bs[krow][c4 + 3] = b.w;
        __syncthreads();
#pragma unroll
        for (int k = 0; k < 16; k++) {
            float av[4], bv[4];
#pragma unroll
            for (int i = 0; i < 4; i++) av[i] = As[k][ty * 4 + i];
#pragma unroll
            for (int j = 0; j < 4; j++) bv[j] = Bs[k][tx * 4 + j];
#pragma unroll
            for (int i = 0; i < 4; i++)
#pragma unroll
                for (int j = 0; j < 4; j++) c[i][j] += av[i] * bv[j];
        }
        __syncthreads();
    }
#pragma unroll
    for (int i = 0; i < 4; i++) {
        int lrow = bm + ty * 4 + i;
        int grow = (lrow >> 1) * 8 + n * 2 + (lrow & 1);
#pragma unroll
        for (int j = 0; j < 4; j++)
            g_qW[(size_t)grow * 512 + bn + tx * 4 + j] = c[i][j];
    }
}

// gemm_tok: tokens[row][d] = sum_e ah[row][e] * Wv[n*512+d][e]
__global__ __launch_bounds__(256) void gemm_tok(const float* __restrict__ Wv,
                                                float* __restrict__ out) {
    __shared__ float As[16][68];
    __shared__ float Bs[16][68];
    int tid = threadIdx.x;
    int n = blockIdx.z;
    int bm = blockIdx.y * 64, bn = blockIdx.x * 64;
    int r = tid >> 2, q4 = (tid & 3) * 4;
    int ty = tid >> 4, tx = tid & 15;
    float c[4][4] = {};
    int lr = bm + r;
    int grow_r = (lr >> 1) * 8 + n * 2 + (lr & 1);
#pragma unroll 1
    for (int kt = 0; kt < 32; kt++) {
        float4 a = *(const float4*)&g_ah[(size_t)grow_r * 512 + kt * 16 + q4];
        float4 b = *(const float4*)&Wv[(size_t)(n * 512 + bn + r) * 512 + kt * 16 + q4];
        As[q4 + 0][r] = a.x; As[q4 + 1][r] = a.y; As[q4 + 2][r] = a.z; As[q4 + 3][r] = a.w;
        Bs[q4 + 0][r] = b.x; Bs[q4 + 1][r] = b.y; Bs[q4 + 2][r] = b.z; Bs[q4 + 3][r] = b.w;
        __syncthreads();
#pragma unroll
        for (int k = 0; k < 16; k++) {
            float av[4], bv[4];
#pragma unroll
            for (int i = 0; i < 4; i++) av[i] = As[k][ty * 4 + i];
#pragma unroll
            for (int j = 0; j < 4; j++) bv[j] = Bs[k][tx * 4 + j];
#pragma unroll
            for (int i = 0; i < 4; i++)
#pragma unroll
                for (int j = 0; j < 4; j++) c[i][j] += av[i] * bv[j];
        }
        __syncthreads();
    }
#pragma unroll
    for (int i = 0; i < 4; i++) {
        int lrow = bm + ty * 4 + i;
        int grow = (lrow >> 1) * 8 + n * 2 + (lrow & 1);
#pragma unroll
        for (int j = 0; j < 4; j++)
            out[(size_t)grow * 512 + bn + tx * 4 + j] = c[i][j];
    }
}

// =====================================================================
// rms_fold
// =====================================================================
__global__ __launch_bounds__(256) void rms_fold(
    const float* __restrict__ qnw, const float* __restrict__ knw) {
    __shared__ float sred[8];
    int r = blockIdx.x, tid = threadIdx.x, warp = tid >> 5, lane = tid & 31;
    float v0 = g_qtmp[(size_t)r * 512 + tid];
    float v1 = g_qtmp[(size_t)r * 512 + tid + 256];
    float ss = warp_sum(v0 * v0 + v1 * v1);
    if (lane == 0) sred[warp] = ss;
    __syncthreads();
    if (tid == 0) {
        float t = 0.f;
#pragma unroll
        for (int i = 0; i < 8; i++) t += sred[i];
        sred[0] = rsqrtf(t * (1.0f / ND) + EPSV);
    }
    __syncthreads();
    float rn = sred[0];
    g_qprime[(size_t)r * 512 + tid] = v0 * rn * (1.f + qnw[tid]) * (1.f + knw[tid]);
    g_qprime[(size_t)r * 512 + tid + 256] =
        v1 * rn * (1.f + qnw[tid + 256]) * (1.f + knw[tid + 256]);
}

// =====================================================================
// knorm_mma v2: CTA 128x256, warp tile 64x64, BK=32, 3-stage cp.async.
// grid (8, 256), 256 threads, 1 CTA/SM.
// =====================================================================
#define BKB 32
#define RSTR 80
#define A_BYTES (128 * RSTR)         /* 10240 */
#define B_BYTES (256 * RSTR)         /* 20480 */
#define STG (A_BYTES + B_BYTES)      /* 30720 */
#define NSTG 3
#define KSTEPS (ND / BKB)            /* 16 */

__global__ __launch_bounds__(256, 1) void knorm_mma() {
    extern __shared__ char dsm[];
    uint32_t sbase = smem_u32(dsm);

    int tid = threadIdx.x, lane = tid & 31, wid = tid >> 5;
    int wm = wid & 1, wn = wid >> 1;        // warp grid 2(m) x 4(n)
    int bm = blockIdx.y * 128;
    int bn = blockIdx.x * 256;

    int lr = tid >> 2, lq = tid & 3;
    auto load_stage = [&](int kt, int s) {
        uint32_t sb = sbase + s * STG;
#pragma unroll
        for (int i = 0; i < 2; i++) {
            int row = lr + i * 64;
            const __nv_bfloat16* g = g_Ha + (size_t)(bm + row) * ND + kt * BKB + lq * 8;
            cp16(sb + row * RSTR + lq * 16, g);
        }
#pragma unroll
        for (int i = 0; i < 4; i++) {
            int row = lr + i * 64;
            const __nv_bfloat16* g = g_Wb + (size_t)(bn + row) * ND + kt * BKB + lq * 8;
            cp16(sb + A_BYTES + row * RSTR + lq * 16, g);
        }
        CP_COMMIT();
    };

    load_stage(0, 0);
    load_stage(1, 1);

    float c[4][8][4];
#pragma unroll
    for (int mt = 0; mt < 4; mt++)
#pragma unroll
        for (int nt = 0; nt < 8; nt++)
#pragma unroll
            for (int t = 0; t < 4; t++) c[mt][nt][t] = 0.f;

    int a_row = lane & 15, a_colb = (lane >> 4) * 16;
    int bg = lane >> 3;
    int b_row = (bg >> 1) * 8 + (lane & 7), b_colb = (bg & 1) * 16;

#pragma unroll 1
    for (int kt = 0; kt < KSTEPS; kt++) {
        int s = kt - (kt / 3) * 3;
        CP_WAIT1();
        __syncthreads();
        if (kt + 2 < KSTEPS) load_stage(kt + 2, (kt + 2) - ((kt + 2) / 3) * 3);
        else CP_COMMIT();

        uint32_t sA = sbase + s * STG;
        uint32_t sB = sA + A_BYTES;
#pragma unroll
        for (int ks = 0; ks < 2; ks++) {
            uint32_t af[4][4];
#pragma unroll
            for (int mt = 0; mt < 4; mt++) {
                uint32_t addr = sA + (wm * 64 + mt * 16 + a_row) * RSTR + ks * 32 + a_colb;
                ldmx4(addr, af[mt][0], af[mt][1], af[mt][2], af[mt][3]);
            }
            uint32_t bf[4][4];
#pragma unroll
            for (int nt2 = 0; nt2 < 4; nt2++) {
                uint32_t addr = sB + (wn * 64 + nt2 * 16 + b_row) * RSTR + ks * 32 + b_colb;
                ldmx4(addr, bf[nt2][0], bf[nt2][1], bf[nt2][2], bf[nt2][3]);
            }
#pragma unroll
            for (int mt = 0; mt < 4; mt++)
#pragma unroll
                for (int nt = 0; nt < 8; nt++)
                    mma16816(c[mt][nt], af[mt],
                             bf[nt >> 1][(nt & 1) * 2 + 0],
                             bf[nt >> 1][(nt & 1) * 2 + 1]);
        }
    }

    // ---- epilogue: per-row sumsq over this CTA's 256 cols ----
    __syncthreads();
    float* red = (float*)dsm;       // [4 wn][128 rows]

#pragma unroll
    for (int mt = 0; mt < 4; mt++) {
        float a = 0.f, b = 0.f;
#pragma unroll
        for (int nt = 0; nt < 8; nt++) {
            a += c[mt][nt][0] * c[mt][nt][0] + c[mt][nt][1] * c[mt][nt][1];
            b += c[mt][nt][2] * c[mt][nt][2] + c[mt][nt][3] * c[mt][nt][3];
        }
        a += __shfl_xor_sync(0xffffffffu, a, 1);
        a += __shfl_xor_sync(0xffffffffu, a, 2);
        b += __shfl_xor_sync(0xffffffffu, b, 1);
        b += __shfl_xor_sync(0xffffffffu, b, 2);
        if ((lane & 3) == 0) {
            int r0 = wm * 64 + mt * 16 + (lane >> 2);
            red[wn * 128 + r0] = a;
            red[wn * 128 + r0 + 8] = b;
        }
    }
    __syncthreads();
    if (tid < 128) {
        float s = red[tid] + red[128 + tid] + red[256 + tid] + red[384 + tid];
        int row = bm + tid;
        int head = blockIdx.x >> 1, sub = blockIdx.x & 1;
        g_part[((size_t)row * NKV + head) * 2 + sub] = s;
    }
}

// =====================================================================
// rnorm_fin
// =====================================================================
__global__ void rnorm_fin() {
    int i = blockIdx.x * 256 + threadIdx.x;
    float s = g_part[i * 2 + 0] + g_part[i * 2 + 1];
    g_rnorm[i] = rsqrtf(s * (1.0f / ND) + EPSV);
}

// =====================================================================
// attn_scores: grid (NB, 4 key-chunks), 256 threads.
// scores[b][h][s] = rnorm * SCALE * dot(qW[h], hist[b,s,:]) + bias
// =====================================================================
__global__ __launch_bounds__(256) void attn_scores(
    const float* __restrict__ hist, const unsigned int* __restrict__ mask) {
    __shared__ float sqW[8][512];
    int b = blockIdx.x, sc = blockIdx.y;
    int tid = threadIdx.x, warp = tid >> 5, lane = tid & 31;
    const float NEGINF = __int_as_float(0xff800000);

    for (int i = tid; i < 8 * 512; i += 256)
        ((float*)sqW)[i] = g_qW[(size_t)b * 4096 + i];
    __syncthreads();

    const float* hb = hist + (size_t)b * NS * ND;
    for (int s0 = warp; s0 < 128; s0 += 8) {
        int s = sc * 128 + s0;
        const float* hrow = hb + (size_t)s * ND;
        float acc[8] = {};
#pragma unroll
        for (int j = 0; j < 16; j++) {
            int d = lane + 32 * j;
            float h = hrow[d];
#pragma unroll
            for (int t = 0; t < 8; t++) acc[t] += h * sqW[t][d];
        }
#pragma unroll
        for (int t = 0; t < 8; t++) acc[t] = warp_sum(acc[t]);
        if (lane == 0) {
            float bias = (mask[b * NS + s] != 0u) ? NEGINF : 0.f;
#pragma unroll
            for (int t = 0; t < 8; t++) {
                float rn = g_rnorm[((size_t)b * NS + s) * NKV + (t >> 1)];
                g_scores[((size_t)(b * NT + t)) * NS + s] = acc[t] * rn * SCALEV + bias;
            }
        }
    }
}

// =====================================================================
// attn_soft: grid NB, 512 threads. Softmax per head; thread owns key s=tid.
// Writes attn weights to out tail AND back into g_scores.
// =====================================================================
__global__ __launch_bounds__(512) void attn_soft(float* __restrict__ out) {
    __shared__ float red[16];
    int b = blockIdx.x;
    int tid = threadIdx.x, warp = tid >> 5, lane = tid & 31;
    float* wout = out + (size_t)NB * NT * ND;

#pragma unroll 1
    for (int h = 0; h < 8; h++) {
        size_t base = ((size_t)(b * NT + h)) * NS;
        float v = g_scores[base + tid];
        float m = warp_max(v);
        if (lane == 0) red[warp] = m;
        __syncthreads();
        if (tid == 0) {
            float mm = red[0];
#pragma unroll
            for (int i = 1; i < 16; i++) mm = fmaxf(mm, red[i]);
            red[0] = mm;
        }
        __syncthreads();
        float bm = red[0];
        __syncthreads();
        float e = __expf(v - bm);
        float sm = warp_sum(e);
        if (lane == 0) red[warp] = sm;
        __syncthreads();
        if (tid == 0) {
            float t = 0.f;
#pragma unroll
            for (int i = 0; i < 16; i++) t += red[i];
            red[0] = t;
        }
        __syncthreads();
        float a = e * (1.0f / red[0]);
        __syncthreads();
        g_scores[base + tid] = a;
        wout[base + tid] = a;
    }
}

// =====================================================================
// attn_av: grid (NB, 4 d-chunks), 256 threads.
// g_ah[b*8+h][d] = sum_s attn[h][s] * hist[b,s,d], split-s reduction.
// =====================================================================
__global__ __launch_bounds__(256) void attn_av(const float* __restrict__ hist) {
    __shared__ float sat[8][512];
    __shared__ float red2[2][8][128];
    int b = blockIdx.x, dc = blockIdx.y;
    int tid = threadIdx.x;

    for (int i = tid; i < 8 * 512; i += 256)
        ((float*)sat)[i] = g_scores[(size_t)b * 4096 + i];
    __syncthreads();

    int d = dc * 128 + (tid & 127);
    int half = tid >> 7;
    const float* hb = hist + (size_t)b * NS * ND;
    float c[8] = {};
    int s0 = half * 256;
#pragma unroll 4
    for (int s = s0; s < s0 + 256; s++) {
        float h = hb[(size_t)s * ND + d];
#pragma unroll
        for (int t = 0; t < 8; t++) c[t] += sat[t][s] * h;
    }
#pragma unroll
    for (int t = 0; t < 8; t++) red2[half][t][tid & 127] = c[t];
    __syncthreads();
    if (half == 0) {
#pragma unroll
        for (int t = 0; t < 8; t++)
            g_ah[((size_t)(b * NT + t)) * ND + d] = red2[0][t][tid] + red2[1][t][tid];
    }
}

// =====================================================================
extern "C" void kernel_launch(void* const* d_in, const int* in_sizes, int n_in,
                              void* d_out, int out_size) {
    const float* target = (const float*)d_in[0];
    const float* hist   = (const float*)d_in[1];
    const unsigned int* mask = (const unsigned int*)d_in[2];
    const float* wq  = (const float*)d_in[3];
    const float* wk  = (const float*)d_in[4];
    const float* wv  = (const float*)d_in[5];
    const float* qnw = (const float*)d_in[6];
    const float* knw = (const float*)d_in[7];
    float* out = (float*)d_out;

    const int SMEM = NSTG * STG;   // 92160
    cudaFuncSetAttribute(knorm_mma, cudaFuncAttributeMaxDynamicSharedMemorySize, SMEM);

    conv_h<<<NROWS * ND / 4 / 256, 256>>>(hist);
    conv_w<<<2048 * ND / 4 / 256, 256>>>(wk);
    gemm_q<<<dim3(8, 8), 256>>>(target, wq);
    rms_fold<<<NB * NT, 256>>>(qnw, knw);
    gemm_qw<<<dim3(8, 2, 4), 256>>>(wk);
    knorm_mma<<<dim3(8, 256), 256, SMEM>>>();
    rnorm_fin<<<(NB * NS * NKV) / 256, 256>>>();
    attn_scores<<<dim3(NB, 4), 256>>>(hist, mask);
    attn_soft<<<NB, 512>>>(out);
    attn_av<<<dim3(NB, 4), 256>>>(hist);
    gemm_tok<<<dim3(8, 2, 4), 256>>>(wv, out);
}